// round 16
// baseline (speedup 1.0000x reference)
#include <cuda_runtime.h>

// ProteinCRF: batched linear-chain CRF NLL.  B=2048, L=2048, T=8.
// out: scalar f32 = mean(denom - num)
//
// R15: ASSOCIATIVE MATRIX SCAN -- serial depth 2048 -> 512.
//  beta_t = D_t E^T beta_{t-1} is linear, so segment operators compose.
//  4 segments x 512 steps per batch. Segment 0 scans the real init vector;
//  segments 1..3 build their 8x8 operator as 8 basis-column vector scans.
//  One warp = one batch (lane = 8*seg + col) -> 2048 warps, ~3.5/SMSP:
//  throughput-bound, stalls overlapped by the arbiter.
//  Step: 2 broadcast LDS.128 + 8 exp + 32 fma.f32x2 (swap-pair matvec,
//  no dup-packs) + act-freeze. Unconditional renorm/8 (eacc-compensated,
//  frozen-lane safe). cp.async double-buffered staging (4x256B/chunk/warp).
//  Combine: 3 exponent-aware 8x8 folds in smem per warp (once).
//  AUX kernel (R12, measured ~10us): len, tag-path numerator, packed tags.
//  Deterministic: fixed-order folds + last-block-arrives mean.

#define CRF_B 2048
#define CRF_L 2048
#define CRF_T 8
#define SEGLEN 512
#define NCH    64          // chunks per segment
#define NWORDS 256         // ptag words per batch
#define SCAN_BLOCKS 256    // 8 warps (batches) per block

__device__ float        g_llh[CRF_B];
__device__ float        g_numpart[CRF_B];
__device__ int          g_len[CRF_B];
__device__ unsigned     g_ptags[CRF_B * NWORDS];
__device__ unsigned int g_count = 0;

#define PACK2(out, lo, hi) \
    asm("mov.b64 %0, {%1, %2};" : "=l"(out) : "f"(lo), "f"(hi))
#define UNPACK2(lo, hi, in) \
    asm("mov.b64 {%0, %1}, %2;" : "=f"(lo), "=f"(hi) : "l"(in))
#define FMA2(d, a, b, c) \
    asm("fma.rn.f32x2 %0, %1, %2, %3;" : "=l"(d) : "l"(a), "l"(b), "l"(c))
#define MUL2(d, a, b) \
    asm("mul.rn.f32x2 %0, %1, %2;" : "=l"(d) : "l"(a), "l"(b))

#define CPASYNC16(dst_u32, src_ptr) \
    asm volatile("cp.async.cg.shared.global [%0], [%1], 16;" \
                 :: "r"(dst_u32), "l"(src_ptr) : "memory")
#define CP_COMMIT()  asm volatile("cp.async.commit_group;" ::: "memory")
#define CP_WAIT1()   asm volatile("cp.async.wait_group 1;" ::: "memory")
#define CP_WAIT0()   asm volatile("cp.async.wait_group 0;" ::: "memory")

// ===================== AUX: tags -> len, numpart, packed ====================
__global__ __launch_bounds__(256)
void crf_aux_kernel(const int* __restrict__ tagsw,
                    const float* __restrict__ transitions,
                    const float* __restrict__ start_tr,
                    const float* __restrict__ end_tr)
{
    __shared__ float s_trans[64];
    __shared__ float s_start[8];
    __shared__ float s_end[8];
    __shared__ float s_sum[8];
    __shared__ int   s_cnt[8];

    const int tid  = threadIdx.x;
    const int lane = tid & 31;
    const int wid  = tid >> 5;
    if (tid < 64) s_trans[tid] = transitions[tid];
    if (tid < 8)  { s_start[tid] = start_tr[tid]; s_end[tid] = end_tr[tid]; }
    __syncthreads();

    const int tstride = (tagsw[1] == 0) ? 2 : 1;   // int64 vs int32 tags
    const int batch   = blockIdx.x;
    const int* tg     = tagsw + (size_t)batch * CRF_L * tstride;

    int lt[8];
    if (tstride == 2) {
        const int4* p = (const int4*)(tg + tid * 16);
        int4 a = p[0], b = p[1], c = p[2], d = p[3];
        lt[0] = a.x; lt[1] = a.z; lt[2] = b.x; lt[3] = b.z;
        lt[4] = c.x; lt[5] = c.z; lt[6] = d.x; lt[7] = d.z;
    } else {
        const int4* p = (const int4*)(tg + tid * 8);
        int4 a = p[0], b = p[1];
        lt[0] = a.x; lt[1] = a.y; lt[2] = a.z; lt[3] = a.w;
        lt[4] = b.x; lt[5] = b.y; lt[6] = b.z; lt[7] = b.w;
    }

    unsigned w = 0;
#pragma unroll
    for (int i = 0; i < 8; i++) w |= (unsigned)(lt[i] & 15) << (4 * i);
    g_ptags[batch * NWORDS + tid] = w;

    int prev = (tid == 0) ? 0 : tg[(tid * 8 - 1) * tstride];
    float s  = 0.0f;
    int  cnt = 0;
#pragma unroll
    for (int i = 0; i < 8; i++) {
        if (lt[i] != 0) {
            cnt++;
            s += (tid == 0 && i == 0) ? s_start[lt[0] - 1]
                                      : s_trans[(prev - 1) * 8 + (lt[i] - 1)];
        }
        prev = lt[i];
    }

#pragma unroll
    for (int off = 16; off > 0; off >>= 1) {
        s   += __shfl_xor_sync(0xFFFFFFFFu, s, off);
        cnt += __shfl_xor_sync(0xFFFFFFFFu, cnt, off);
    }
    if (lane == 0) { s_sum[wid] = s; s_cnt[wid] = cnt; }
    __syncthreads();
    if (tid == 0) {
        float tot = 0.0f; int len = 0;
#pragma unroll
        for (int i = 0; i < 8; i++) { tot += s_sum[i]; len += s_cnt[i]; }
        const int last = tg[(len - 1) * tstride] - 1;
        g_numpart[batch] = tot + s_end[last];
        g_len[batch]     = len;
    }
}

// ===================== SCAN: segmented matrix scan ==========================
__device__ __forceinline__ float sel8(float4 lo, float4 hi, int c) {
    int cc = c & 7;
    float s01 = (cc & 1) ? lo.y : lo.x;
    float s23 = (cc & 1) ? lo.w : lo.z;
    float s45 = (cc & 1) ? hi.y : hi.x;
    float s67 = (cc & 1) ? hi.w : hi.z;
    float s03 = (cc & 2) ? s23 : s01;
    float s47 = (cc & 2) ? s67 : s45;
    return (cc & 4) ? s47 : s03;
}

__device__ __forceinline__ float scalef(int d) {   // 2^d for d <= 0
    return (d <= -126) ? 0.0f : __int_as_float((127 + d) << 23);
}

__global__ __launch_bounds__(256, 2)
void crf_scan_kernel(const float* __restrict__ emissions,
                     const float* __restrict__ transitions,
                     const float* __restrict__ end_tr,
                     const float* __restrict__ start_tr,
                     float*       __restrict__ out)
{
    __shared__ __align__(16) float s_em[8][2][272];  // warp, buf, 4*68 floats
    __shared__ int   s_ea[8][32];
    __shared__ float s_es[8][32];
    __shared__ double s_red[8];
    __shared__ bool  s_lastb;

    const int tid  = threadIdx.x;
    const int lane = tid & 31;
    const int wid  = tid >> 5;
    const int seg  = lane >> 3;     // 0..3
    const int col  = lane & 7;      // 0..7
    const int batch = blockIdx.x * 8 + wid;

    const float* em_base = emissions + (size_t)batch * (CRF_L * CRF_T);
    const unsigned base_s =
        (unsigned)__cvta_generic_to_shared(&s_em[wid][0][0]);

    // ---- staging: lane copies pieces (lane) and (lane+32) of 64 ------------
#define FILLC(C, BUF) { \
    const int c_ = (C); \
    { int p = lane;      int sp = p >> 4, of = p & 15; \
      CPASYNC16(base_s + ((BUF) * 272 + sp * 68 + of * 4) * 4, \
                em_base + sp * 4096 + c_ * 64 + of * 4); } \
    { int p = lane + 32; int sp = p >> 4, of = p & 15; \
      CPASYNC16(base_s + ((BUF) * 272 + sp * 68 + of * 4) * 4, \
                em_base + sp * 4096 + c_ * 64 + of * 4); } \
    CP_COMMIT(); }

    FILLC(0, 0)
    FILLC(1, 1)

    const int   len     = g_len[batch];
    const float numpart = g_numpart[batch];
    const unsigned* ptg = g_ptags + batch * NWORDS + seg * NCH;

    // E in swap-pair layout:
    // EN[pi][q] = (E[2pi][2q],   E[2pi+1][2q+1])
    // ES[pi][q] = (E[2pi+1][2q], E[2pi][2q+1])
    unsigned long long EN[4][4], ES[4][4];
#pragma unroll
    for (int pi = 0; pi < 4; pi++)
#pragma unroll
        for (int q = 0; q < 4; q++) {
            float e00 = __expf(transitions[(2*pi)   * 8 + 2*q]);
            float e11 = __expf(transitions[(2*pi+1) * 8 + 2*q+1]);
            float e10 = __expf(transitions[(2*pi+1) * 8 + 2*q]);
            float e01 = __expf(transitions[(2*pi)   * 8 + 2*q+1]);
            PACK2(EN[pi][q], e00, e11);
            PACK2(ES[pi][q], e10, e01);
        }

    // act window: t in [act_lo, act_hi)
    const int act_lo = (seg == 0) ? 1 : (seg << 9);
    int act_hi = (seg + 1) << 9;  if (act_hi > len) act_hi = len;
    int span_i = act_hi - act_lo; if (span_i < 0) span_i = 0;
    const unsigned uspan = (unsigned)span_i;
    const bool is_c0 = (col == 0);

    CP_WAIT1();
    __syncwarp();

    // ---- init ---------------------------------------------------------------
    float m0, t0term;
    unsigned long long vp[4];
    int   eacc = 0;
    float emsum = 0.0f;
    {
        float4 lo0 = *(const float4*)&s_em[wid][0][0];
        float4 hi0 = *(const float4*)&s_em[wid][0][4];
        float a[8] = { start_tr[0]+lo0.x, start_tr[1]+lo0.y,
                       start_tr[2]+lo0.z, start_tr[3]+lo0.w,
                       start_tr[4]+hi0.x, start_tr[5]+hi0.y,
                       start_tr[6]+hi0.z, start_tr[7]+hi0.w };
        m0 = a[0];
#pragma unroll
        for (int i = 1; i < 8; i++) m0 = fmaxf(m0, a[i]);
        float v[8];
#pragma unroll
        for (int i = 0; i < 8; i++) {
            float b0v = __expf(a[i] - m0);
            v[i] = (seg == 0) ? b0v : ((i == col) ? 1.0f : 0.0f);
        }
#pragma unroll
        for (int q = 0; q < 4; q++) PACK2(vp[q], v[2*q], v[2*q+1]);
        unsigned w0 = ptg[0];   // for seg 0 this is word 0
        t0term = sel8(lo0, hi0, (int)(w0 & 15u) - 1);
    }

    unsigned wt = ptg[0];

    // ---- main loop: 64 chunks x 8 steps ------------------------------------
    for (int k = 0; k < NCH; k++) {
        const int buf = k & 1;
        const unsigned wtn = ptg[min(k + 1, NCH - 1)];
        const int off_act = (seg << 9) + (k << 3) - act_lo;
        const float* sp = &s_em[wid][buf][seg * 68];

#pragma unroll
        for (int j = 0; j < 8; j++) {
            const bool act = (unsigned)(off_act + j) < uspan;
            float4 lo = *(const float4*)(sp + j * 8);
            float4 hi = *(const float4*)(sp + j * 8 + 4);

            // unpack current v, build swapped pairs
            float v0,v1,v2,v3,v4,v5,v6,v7;
            UNPACK2(v0,v1,vp[0]); UNPACK2(v2,v3,vp[1]);
            UNPACK2(v4,v5,vp[2]); UNPACK2(v6,v7,vp[3]);
            unsigned long long vs0,vs1,vs2,vs3;
            PACK2(vs0, v1, v0); PACK2(vs1, v3, v2);
            PACK2(vs2, v5, v4); PACK2(vs3, v7, v6);

            // d[q] = sum_pi vp[pi]*EN[pi][q] + vs[pi]*ES[pi][q]
            unsigned long long d0,d1,d2,d3;
            MUL2(d0, vp[0], EN[0][0]); MUL2(d1, vp[0], EN[0][1]);
            MUL2(d2, vp[0], EN[0][2]); MUL2(d3, vp[0], EN[0][3]);
            FMA2(d0, vp[1], EN[1][0], d0); FMA2(d1, vp[1], EN[1][1], d1);
            FMA2(d2, vp[1], EN[1][2], d2); FMA2(d3, vp[1], EN[1][3], d3);
            FMA2(d0, vp[2], EN[2][0], d0); FMA2(d1, vp[2], EN[2][1], d1);
            FMA2(d2, vp[2], EN[2][2], d2); FMA2(d3, vp[2], EN[2][3], d3);
            FMA2(d0, vp[3], EN[3][0], d0); FMA2(d1, vp[3], EN[3][1], d1);
            FMA2(d2, vp[3], EN[3][2], d2); FMA2(d3, vp[3], EN[3][3], d3);
            FMA2(d0, vs0, ES[0][0], d0); FMA2(d1, vs0, ES[0][1], d1);
            FMA2(d2, vs0, ES[0][2], d2); FMA2(d3, vs0, ES[0][3], d3);
            FMA2(d0, vs1, ES[1][0], d0); FMA2(d1, vs1, ES[1][1], d1);
            FMA2(d2, vs1, ES[1][2], d2); FMA2(d3, vs1, ES[1][3], d3);
            FMA2(d0, vs2, ES[2][0], d0); FMA2(d1, vs2, ES[2][1], d1);
            FMA2(d2, vs2, ES[2][2], d2); FMA2(d3, vs2, ES[2][3], d3);
            FMA2(d0, vs3, ES[3][0], d0); FMA2(d1, vs3, ES[3][1], d1);
            FMA2(d2, vs3, ES[3][2], d2); FMA2(d3, vs3, ES[3][3], d3);

            // * exp(em)
            unsigned long long ep;
            PACK2(ep, __expf(lo.x), __expf(lo.y)); MUL2(d0, d0, ep);
            PACK2(ep, __expf(lo.z), __expf(lo.w)); MUL2(d1, d1, ep);
            PACK2(ep, __expf(hi.x), __expf(hi.y)); MUL2(d2, d2, ep);
            PACK2(ep, __expf(hi.z), __expf(hi.w)); MUL2(d3, d3, ep);

            // emission-path numerator (col 0 lanes only)
            float es = sel8(lo, hi, (int)((wt >> (4 * j)) & 15u) - 1);
            emsum += (act && is_c0) ? es : 0.0f;

            // act-freeze
            vp[0] = act ? d0 : vp[0];  vp[1] = act ? d1 : vp[1];
            vp[2] = act ? d2 : vp[2];  vp[3] = act ? d3 : vp[3];

            // per-chunk renorm: unconditional, eacc-compensated (exact)
            if (j == 7) {
                float r0,r1,r2,r3,r4,r5,r6,r7;
                UNPACK2(r0,r1,vp[0]); UNPACK2(r2,r3,vp[1]);
                UNPACK2(r4,r5,vp[2]); UNPACK2(r6,r7,vp[3]);
                float m = fmaxf(fmaxf(fmaxf(r0,r1), fmaxf(r2,r3)),
                                fmaxf(fmaxf(r4,r5), fmaxf(r6,r7)));
                int e = ((__float_as_int(m) >> 23) & 0xFF) - 127;
                float sc = __int_as_float((127 - e) << 23);
                unsigned long long scp; PACK2(scp, sc, sc);
                MUL2(vp[0], vp[0], scp); MUL2(vp[1], vp[1], scp);
                MUL2(vp[2], vp[2], scp); MUL2(vp[3], vp[3], scp);
                eacc += e;
            }
        }
        wt = wtn;

        if (k < NCH - 2) { FILLC(k + 2, buf) CP_WAIT1(); }
        else             { CP_WAIT0(); }
        __syncwarp();
    }

    // ---- combine: 3 exponent-aware 8x8 folds (per warp, in smem) -----------
    float* scr = &s_em[wid][0][0];    // 544 floats of scratch
    {
        float v[8];
        UNPACK2(v[0],v[1],vp[0]); UNPACK2(v[2],v[3],vp[1]);
        UNPACK2(v[4],v[5],vp[2]); UNPACK2(v[6],v[7],vp[3]);
#pragma unroll
        for (int i = 0; i < 8; i++) scr[lane * 9 + i] = v[i];
        s_ea[wid][lane] = eacc;
        s_es[wid][lane] = emsum;
    }
    __syncwarp();

    int expacc = s_ea[wid][0];        // seg0 exponent
    for (int s = 1; s < 4; s++) {
        int Emax = s_ea[wid][8 * s];
#pragma unroll
        for (int c = 1; c < 8; c++) Emax = max(Emax, s_ea[wid][8 * s + c]);

        float pv[8];
#pragma unroll
        for (int c = 0; c < 8; c++)
            pv[c] = (s == 1) ? scr[c] : scr[288 + c];

        float t = 0.0f;
#pragma unroll
        for (int c = 0; c < 8; c++)
            t += scr[(8 * s + c) * 9 + lane]
               * scalef(s_ea[wid][8 * s + c] - Emax) * pv[c];
        __syncwarp();
        scr[288 + lane] = t;
        __syncwarp();

        float m = scr[288];
#pragma unroll
        for (int c2 = 1; c2 < 8; c2++) m = fmaxf(m, scr[288 + c2]);
        int er = ((__float_as_int(m) >> 23) & 0xFF) - 127;
        __syncwarp();
        scr[288 + lane] = t * __int_as_float((127 - er) << 23);
        __syncwarp();
        expacc += Emax + er;
    }

    if (lane == 0) {
        float w = 0.0f;
#pragma unroll
        for (int jx = 0; jx < 8; jx++)
            w += scr[288 + jx] * __expf(end_tr[jx]);
        float denom = m0 + (float)expacc * 0.693147180559945309f + __logf(w);
        float emtot = s_es[wid][0] + s_es[wid][8] + s_es[wid][16]
                    + s_es[wid][24] + t0term;
        g_llh[batch] = denom - (numpart + emtot);
    }

    // ---- last-block-arrives final mean (deterministic) ---------------------
    __threadfence();
    __syncthreads();
    if (tid == 0) {
        unsigned old = atomicAdd(&g_count, 1u);
        s_lastb = (old == (unsigned)(SCAN_BLOCKS - 1));
    }
    __syncthreads();

    if (s_lastb) {
        double sdd = 0.0;
        for (int i = tid; i < CRF_B; i += 256) sdd += (double)__ldcg(&g_llh[i]);
#pragma unroll
        for (int off = 16; off > 0; off >>= 1)
            sdd += __shfl_xor_sync(0xFFFFFFFFu, sdd, off);
        if (lane == 0) s_red[wid] = sdd;
        __syncthreads();
        if (tid == 0) {
            double tot = 0.0;
#pragma unroll
            for (int i2 = 0; i2 < 8; i2++) tot += s_red[i2];
            out[0] = (float)(tot / (double)CRF_B);
            g_count = 0;   // reset for graph replay
        }
    }
}

extern "C" void kernel_launch(void* const* d_in, const int* in_sizes, int n_in,
                              void* d_out, int out_size)
{
    const float* emissions   = (const float*)d_in[0];
    const float* transitions = (const float*)d_in[1];
    const float* start_tr    = (const float*)d_in[2];
    const float* end_tr      = (const float*)d_in[3];
    const int*   tagsw       = (const int*)d_in[4];

    crf_aux_kernel<<<CRF_B, 256>>>(tagsw, transitions, start_tr, end_tr);
    crf_scan_kernel<<<SCAN_BLOCKS, 256>>>(
        emissions, transitions, end_tr, start_tr, (float*)d_out);
}